// round 1
// baseline (speedup 1.0000x reference)
#include <cuda_runtime.h>
#include <math.h>

// Problem dims: N=8, T=64, F=512, E=64
#define PITCH 65   // smem row pitch (floats) to dodge bank conflicts

// Scratch in projected+transposed layout [n][e][f][t]  (e = projected dim)
__device__ float g_Qp[8u * 64u * 512u * 64u];
__device__ float g_Kp[8u * 64u * 512u * 64u];
__device__ float g_Vp[8u * 64u * 512u * 64u];
__device__ float g_Op[8u * 64u * 512u * 64u];   // attention output, [n][e][q][t]

// ---------------------------------------------------------------------------
// Kernel 1: projection + transpose.
// grid (512 f, 8 n, 3 which), block 256.
// out[n][d][f][t] = sum_e in[n][t][f][e] * W[d][e]
// ---------------------------------------------------------------------------
__global__ __launch_bounds__(256) void proj_kernel(
    const float* __restrict__ qin, const float* __restrict__ kin,
    const float* __restrict__ vin, const float* __restrict__ Wq,
    const float* __restrict__ Wk, const float* __restrict__ Wv)
{
    __shared__ float sW[64 * PITCH];   // [d][e]
    __shared__ float sIn[64 * PITCH];  // [t][e]

    const int f = blockIdx.x, n = blockIdx.y, w = blockIdx.z;
    const float* in; const float* W; float* out;
    if (w == 0)      { in = qin; W = Wq; out = g_Qp; }
    else if (w == 1) { in = kin; W = Wk; out = g_Kp; }
    else             { in = vin; W = Wv; out = g_Vp; }

    const int tid = threadIdx.x;
    #pragma unroll
    for (int i = tid; i < 4096; i += 256)
        sW[(i >> 6) * PITCH + (i & 63)] = W[i];

    const float* inb = in + ((size_t)n * 64 * 512 + f) * 64;
    #pragma unroll
    for (int i = tid; i < 1024; i += 256) {
        int t = i >> 4, c = (i & 15) * 4;
        float4 v = *(const float4*)(inb + (size_t)t * (512 * 64) + c);
        float* d = &sIn[t * PITCH + c];
        d[0] = v.x; d[1] = v.y; d[2] = v.z; d[3] = v.w;
    }
    __syncthreads();

    const int ty = tid >> 4, tx = tid & 15;
    float acc[4][4] = {};
    #pragma unroll
    for (int e = 0; e < 64; e++) {
        float a[4], b[4];
        #pragma unroll
        for (int i = 0; i < 4; i++) a[i] = sW[(ty * 4 + i) * PITCH + e];
        #pragma unroll
        for (int j = 0; j < 4; j++) b[j] = sIn[(tx * 4 + j) * PITCH + e];
        #pragma unroll
        for (int i = 0; i < 4; i++)
            #pragma unroll
            for (int j = 0; j < 4; j++)
                acc[i][j] = fmaf(a[i], b[j], acc[i][j]);
    }

    float* ob = out + ((size_t)n * 64 * 512 + f) * 64;   // [d][f][t] base at this (n,f)
    #pragma unroll
    for (int i = 0; i < 4; i++) {
        float4 v = make_float4(acc[i][0], acc[i][1], acc[i][2], acc[i][3]);
        *(float4*)(ob + (size_t)(ty * 4 + i) * (512 * 64) + tx * 4) = v;
    }
}

// ---------------------------------------------------------------------------
// Kernel 2: fused attention per (n, e) with online softmax over k.
// grid (8 qblocks, 64 e, 8 n), block 256.
// O[q][t] = softmax_k( (1/8) * sum_t' Q[q][t']K[k][t'] ) @ V[k][t]
// Dynamic smem: sQ,sK,sV,sP each 64*PITCH floats.
// ---------------------------------------------------------------------------
__global__ __launch_bounds__(256) void attn_kernel()
{
    extern __shared__ float sh[];
    float* sQ = sh;
    float* sK = sQ + 64 * PITCH;
    float* sV = sK + 64 * PITCH;
    float* sP = sV + 64 * PITCH;
    __shared__ float sm_m[64], sm_l[64], sm_sc[64];

    const int qb = blockIdx.x, e = blockIdx.y, n = blockIdx.z;
    const size_t base = (size_t)(n * 64 + e) * 512 * 64;
    const float* Qg = g_Qp + base + (size_t)qb * 64 * 64;
    const float* Kg = g_Kp + base;
    const float* Vg = g_Vp + base;

    const int tid = threadIdx.x, ty = tid >> 4, tx = tid & 15;

    #pragma unroll
    for (int i = tid; i < 1024; i += 256) {
        int r = i >> 4, c = (i & 15) * 4;
        float4 v = *(const float4*)(Qg + r * 64 + c);
        float* d = &sQ[r * PITCH + c];
        d[0] = v.x; d[1] = v.y; d[2] = v.z; d[3] = v.w;
    }
    if (tid < 64) { sm_m[tid] = -1e30f; sm_l[tid] = 0.0f; }

    float o[4][4] = {};

    for (int kc = 0; kc < 8; kc++) {
        __syncthreads();   // previous GEMM2 done reading sK/sV
        #pragma unroll
        for (int i = tid; i < 1024; i += 256) {
            int r = i >> 4, c = (i & 15) * 4;
            size_t off = (size_t)(kc * 64 + r) * 64 + c;
            float4 kv = *(const float4*)(Kg + off);
            float4 vv = *(const float4*)(Vg + off);
            float* dk = &sK[r * PITCH + c];
            dk[0] = kv.x; dk[1] = kv.y; dk[2] = kv.z; dk[3] = kv.w;
            float* dv = &sV[r * PITCH + c];
            dv[0] = vv.x; dv[1] = vv.y; dv[2] = vv.z; dv[3] = vv.w;
        }
        __syncthreads();

        // GEMM1: S[q][k] = sum_t Q[q][t]*K[k][t]
        float s[4][4] = {};
        #pragma unroll
        for (int t = 0; t < 64; t++) {
            float a[4], b[4];
            #pragma unroll
            for (int i = 0; i < 4; i++) a[i] = sQ[(ty * 4 + i) * PITCH + t];
            #pragma unroll
            for (int j = 0; j < 4; j++) b[j] = sK[(tx * 4 + j) * PITCH + t];
            #pragma unroll
            for (int i = 0; i < 4; i++)
                #pragma unroll
                for (int j = 0; j < 4; j++)
                    s[i][j] = fmaf(a[i], b[j], s[i][j]);
        }
        #pragma unroll
        for (int i = 0; i < 4; i++)
            #pragma unroll
            for (int j = 0; j < 4; j++)
                sP[(ty * 4 + i) * PITCH + tx * 4 + j] = s[i][j] * 0.125f;
        __syncthreads();

        // Online softmax per q-row (64 rows handled by threads 0..63)
        if (tid < 64) {
            float m_old = sm_m[tid];
            float mx = m_old;
            float* row = &sP[tid * PITCH];
            #pragma unroll 8
            for (int k = 0; k < 64; k++) mx = fmaxf(mx, row[k]);
            float sum = 0.0f;
            #pragma unroll 8
            for (int k = 0; k < 64; k++) {
                float p = expf(row[k] - mx);
                row[k] = p;
                sum += p;
            }
            float sc = expf(m_old - mx);
            sm_l[tid] = sm_l[tid] * sc + sum;
            sm_m[tid] = mx;
            sm_sc[tid] = sc;
        }
        __syncthreads();

        // rescale running O, then GEMM2: O[q][t] += P[q][k]*V[k][t]
        #pragma unroll
        for (int i = 0; i < 4; i++) {
            float sc = sm_sc[ty * 4 + i];
            #pragma unroll
            for (int j = 0; j < 4; j++) o[i][j] *= sc;
        }
        #pragma unroll
        for (int k = 0; k < 64; k++) {
            float a[4], b[4];
            #pragma unroll
            for (int i = 0; i < 4; i++) a[i] = sP[(ty * 4 + i) * PITCH + k];
            #pragma unroll
            for (int j = 0; j < 4; j++) b[j] = sV[k * PITCH + tx * 4 + j];
            #pragma unroll
            for (int i = 0; i < 4; i++)
                #pragma unroll
                for (int j = 0; j < 4; j++)
                    o[i][j] = fmaf(a[i], b[j], o[i][j]);
        }
    }

    float* Og = g_Op + base + (size_t)qb * 64 * 64;
    #pragma unroll
    for (int i = 0; i < 4; i++) {
        float inv = 1.0f / sm_l[ty * 4 + i];
        float4 v = make_float4(o[i][0] * inv, o[i][1] * inv, o[i][2] * inv, o[i][3] * inv);
        *(float4*)(Og + (size_t)(ty * 4 + i) * 64 + tx * 4) = v;
    }
}

// ---------------------------------------------------------------------------
// Kernel 3: output projection + transpose back.
// grid (512 q, 8 n), block 256.
// out[n][t][q][d] = sum_e Op[n][e][q][t] * Wo[d][e] + bo[d]
// ---------------------------------------------------------------------------
__global__ __launch_bounds__(256) void out_kernel(
    const float* __restrict__ Wo, const float* __restrict__ bo,
    float* __restrict__ out)
{
    __shared__ float sO[64 * PITCH];  // [e][t]
    __shared__ float sW[64 * PITCH];  // [d][e]
    __shared__ float sb[64];

    const int q = blockIdx.x, n = blockIdx.y;
    const int tid = threadIdx.x, ty = tid >> 4, tx = tid & 15;

    #pragma unroll
    for (int i = tid; i < 4096; i += 256)
        sW[(i >> 6) * PITCH + (i & 63)] = Wo[i];
    if (tid < 64) sb[tid] = bo[tid];

    #pragma unroll
    for (int i = tid; i < 1024; i += 256) {
        int er = i >> 4, c = (i & 15) * 4;
        float4 v = *(const float4*)(g_Op + ((size_t)(n * 64 + er) * 512 + q) * 64 + c);
        float* d = &sO[er * PITCH + c];
        d[0] = v.x; d[1] = v.y; d[2] = v.z; d[3] = v.w;
    }
    __syncthreads();

    float acc[4][4] = {};   // [t-sub][d-sub]
    #pragma unroll
    for (int e = 0; e < 64; e++) {
        float a[4], b[4];
        #pragma unroll
        for (int i = 0; i < 4; i++) a[i] = sO[e * PITCH + ty * 4 + i];
        #pragma unroll
        for (int j = 0; j < 4; j++) b[j] = sW[(tx * 4 + j) * PITCH + e];
        #pragma unroll
        for (int i = 0; i < 4; i++)
            #pragma unroll
            for (int j = 0; j < 4; j++)
                acc[i][j] = fmaf(a[i], b[j], acc[i][j]);
    }

    #pragma unroll
    for (int i = 0; i < 4; i++) {
        int t = ty * 4 + i;
        float4 v = make_float4(acc[i][0] + sb[tx * 4 + 0],
                               acc[i][1] + sb[tx * 4 + 1],
                               acc[i][2] + sb[tx * 4 + 2],
                               acc[i][3] + sb[tx * 4 + 3]);
        *(float4*)(out + ((size_t)(n * 64 + t) * 512 + q) * 64 + tx * 4) = v;
    }
}

// ---------------------------------------------------------------------------
extern "C" void kernel_launch(void* const* d_in, const int* in_sizes, int n_in,
                              void* d_out, int out_size)
{
    const float* value = (const float*)d_in[0];
    const float* key   = (const float*)d_in[1];
    const float* query = (const float*)d_in[2];
    const float* Wv    = (const float*)d_in[3];
    const float* Wk    = (const float*)d_in[4];
    const float* Wq    = (const float*)d_in[5];
    const float* Wo    = (const float*)d_in[6];
    const float* bo    = (const float*)d_in[7];
    float* out = (float*)d_out;

    const int attn_smem = 4 * 64 * PITCH * (int)sizeof(float);  // 66560 B
    cudaFuncSetAttribute(attn_kernel,
                         cudaFuncAttributeMaxDynamicSharedMemorySize, attn_smem);

    dim3 g1(512, 8, 3);
    proj_kernel<<<g1, 256>>>(query, key, value, Wq, Wk, Wv);

    dim3 g2(8, 64, 8);
    attn_kernel<<<g2, 256, attn_smem>>>();

    dim3 g3(512, 8);
    out_kernel<<<g3, 256>>>(Wo, bo, out);
}

// round 3
// speedup vs baseline: 1.4324x; 1.4324x over previous
#include <cuda_runtime.h>
#include <cstdint>
#include <math.h>

// Problem dims: N=8, T=64, F=512, E=64
#define PITCH 65

// Arch-feature gate: tcgen05 exists only on sm_100a/sm_103a ('a' targets).
#if defined(__CUDA_ARCH__) && (defined(__CUDA_ARCH_FEAT_SM103_ALL) || \
    defined(__CUDA_ARCH_FEAT_SM100_ALL) || \
    (defined(__CUDA_ARCH_SPECIFIC__) && (__CUDA_ARCH_SPECIFIC__ >= 1000)))
#define ATTN_TCGEN 1
#else
#define ATTN_TCGEN 0
#endif

// Scratch: projected layout [n][e][f][t]
__device__ float g_Qp[8u * 64u * 512u * 64u];
__device__ float g_Kp[8u * 64u * 512u * 64u];
__device__ float g_Vp[8u * 64u * 512u * 64u];
__device__ float g_Op[8u * 64u * 512u * 64u];   // [n][e][q][t]

// ============================================================================
// tcgen05 helpers (only referenced inside the guarded region)
// ============================================================================
__device__ __forceinline__ uint32_t smem_u32(const void* p) {
    uint32_t a;
    asm("{ .reg .u64 t; cvta.to.shared.u64 t, %1; cvt.u32.u64 %0, t; }"
        : "=r"(a) : "l"(p));
    return a;
}
#if ATTN_TCGEN
__device__ __forceinline__ uint32_t elect_one() {
    uint32_t p;
    asm volatile("{\n\t.reg .pred p;\n\telect.sync _|p, 0xFFFFFFFF;\n\t"
                 "selp.b32 %0, 1, 0, p;\n\t}" : "=r"(p));
    return p;
}
#endif
#define MBAR_INIT(a, c) \
    asm volatile("mbarrier.init.shared.b64 [%0], %1;" :: "r"(a), "r"(c) : "memory")
#define MBAR_WAIT(a, ph) do { \
    uint32_t _m = (a), _p = (ph), _d; \
    asm volatile("{\n\t.reg .pred p;\n\t" \
        "mbarrier.try_wait.parity.acquire.cta.shared::cta.b64 p, [%1], %2;\n\t" \
        "selp.b32 %0, 1, 0, p;\n\t}" : "=r"(_d) : "r"(_m), "r"(_p) : "memory"); \
    if (!_d) { \
        asm volatile("{\n\t.reg .pred P1;\n\tWL_%=: \n\t" \
            "mbarrier.try_wait.parity.acquire.cta.shared::cta.b64 P1, [%0], %1, 0x989680;\n\t" \
            "@P1 bra.uni WD_%=;\n\tbra.uni WL_%=;\n\tWD_%=: \n\t}" \
            :: "r"(_m), "r"(_p) : "memory"); \
    } } while (0)

#define TC_ALLOC(sa, n)  asm volatile( \
    "tcgen05.alloc.cta_group::1.sync.aligned.shared::cta.b32 [%0], %1;" \
    :: "r"(sa), "r"(n) : "memory")
#define TC_DEALLOC(t, n) asm volatile( \
    "tcgen05.dealloc.cta_group::1.sync.aligned.b32 %0, %1;" :: "r"(t), "r"(n))
#define TC_RELINQ() asm volatile("tcgen05.relinquish_alloc_permit.cta_group::1.sync.aligned;")
#define TC_COMMIT(mb) asm volatile( \
    "tcgen05.commit.cta_group::1.mbarrier::arrive::one.shared::cluster.b64 [%0];" \
    :: "r"(mb) : "memory")
#define TC_WAIT_LD() asm volatile("tcgen05.wait::ld.sync.aligned;" ::: "memory")
#define TC_FENCE_BEFORE() asm volatile("tcgen05.fence::before_thread_sync;" ::: "memory")
#define TC_FENCE_AFTER()  asm volatile("tcgen05.fence::after_thread_sync;" ::: "memory")
#define FENCE_ASYNC() asm volatile("fence.proxy.async.shared::cta;" ::: "memory")

#define TC_LD_X32(r, ta) asm volatile( \
    "tcgen05.ld.sync.aligned.32x32b.x32.b32 " \
    "{%0,%1,%2,%3,%4,%5,%6,%7,%8,%9,%10,%11,%12,%13,%14,%15," \
    "%16,%17,%18,%19,%20,%21,%22,%23,%24,%25,%26,%27,%28,%29,%30,%31}, [%32];" \
    : "=r"((r)[0]),"=r"((r)[1]),"=r"((r)[2]),"=r"((r)[3]), \
      "=r"((r)[4]),"=r"((r)[5]),"=r"((r)[6]),"=r"((r)[7]), \
      "=r"((r)[8]),"=r"((r)[9]),"=r"((r)[10]),"=r"((r)[11]), \
      "=r"((r)[12]),"=r"((r)[13]),"=r"((r)[14]),"=r"((r)[15]), \
      "=r"((r)[16]),"=r"((r)[17]),"=r"((r)[18]),"=r"((r)[19]), \
      "=r"((r)[20]),"=r"((r)[21]),"=r"((r)[22]),"=r"((r)[23]), \
      "=r"((r)[24]),"=r"((r)[25]),"=r"((r)[26]),"=r"((r)[27]), \
      "=r"((r)[28]),"=r"((r)[29]),"=r"((r)[30]),"=r"((r)[31]) \
    : "r"(ta))

#if ATTN_TCGEN
__device__ __forceinline__ void mma_tf32_ss(uint32_t d, uint64_t a, uint64_t b,
                                            uint32_t idesc, bool en) {
    uint32_t e = en ? 1u : 0u;
    asm volatile(
        "{\n\t.reg .pred p;\n\tsetp.ne.u32 p, %5, 0;\n\t"
        "tcgen05.mma.cta_group::1.kind::tf32 [%0], %1, %2, %3, {%4,%4,%4,%4}, p;\n\t}"
        :: "r"(d), "l"(a), "l"(b), "r"(idesc), "r"(0u), "r"(e) : "memory");
}
#endif

// SMEM desc: SW128, version=1(Blackwell), SBO=64, LBO=1
static __device__ __forceinline__ uint64_t make_desc(uint32_t addr) {
    const uint64_t base = (uint64_t(2) << 61) | (uint64_t(1) << 46) |
                          (uint64_t(64) << 32) | (uint64_t(1) << 16);
    return base | ((uint64_t)(addr >> 4) & 0x3FFF);
}

// idesc kind::tf32: dtype=F32(1<<4), atype=TF32(2<<7), btype=TF32(2<<10),
// N=64 ((64/8)<<17), M=128 ((128/16)<<24)
#define IDESC_TF32 ((1u<<4) | (2u<<7) | (2u<<10) | (8u<<17) | (8u<<24))

// smem layout (bytes), all tiles 1024-aligned
#define SM_TMEM 0
#define SM_MB1  16
#define SM_MB2  24
#define SM_QHI  1024
#define SM_QLO  (SM_QHI + 32768)
#define SM_KHI  (SM_QLO + 32768)
#define SM_KLO  (SM_KHI + 16384)
#define SM_VHI  (SM_KLO + 16384)
#define SM_VLO  (SM_VHI + 16384)
#define SM_PHI  (SM_VLO + 16384)
#define SM_PLO  (SM_PHI + 32768)
#define SM_TOTAL (SM_PLO + 32768)   // 197632 B

__device__ __forceinline__ uint32_t swz(uint32_t off) {
    return off ^ ((off >> 3) & 0x70);
}
__device__ __forceinline__ float hi13(float v) {
    return __uint_as_float(__float_as_uint(v) & 0xFFFFE000u);
}

// ---------------------------------------------------------------------------
// Kernel 1: projection + transpose.
// ---------------------------------------------------------------------------
__global__ __launch_bounds__(256) void proj_kernel(
    const float* __restrict__ qin, const float* __restrict__ kin,
    const float* __restrict__ vin, const float* __restrict__ Wq,
    const float* __restrict__ Wk, const float* __restrict__ Wv)
{
    __shared__ float sW[64 * PITCH];
    __shared__ float sIn[64 * PITCH];

    const int f = blockIdx.x, n = blockIdx.y, w = blockIdx.z;
    const float* in; const float* W; float* out;
    if (w == 0)      { in = qin; W = Wq; out = g_Qp; }
    else if (w == 1) { in = kin; W = Wk; out = g_Kp; }
    else             { in = vin; W = Wv; out = g_Vp; }

    const int tid = threadIdx.x;
    #pragma unroll
    for (int i = tid; i < 4096; i += 256)
        sW[(i >> 6) * PITCH + (i & 63)] = W[i];

    const float* inb = in + ((size_t)n * 64 * 512 + f) * 64;
    #pragma unroll
    for (int i = tid; i < 1024; i += 256) {
        int t = i >> 4, c = (i & 15) * 4;
        float4 v = *(const float4*)(inb + (size_t)t * (512 * 64) + c);
        float* d = &sIn[t * PITCH + c];
        d[0] = v.x; d[1] = v.y; d[2] = v.z; d[3] = v.w;
    }
    __syncthreads();

    const int ty = tid >> 4, tx = tid & 15;
    float acc[4][4] = {};
    #pragma unroll
    for (int e = 0; e < 64; e++) {
        float a[4], b[4];
        #pragma unroll
        for (int i = 0; i < 4; i++) a[i] = sW[(ty * 4 + i) * PITCH + e];
        #pragma unroll
        for (int j = 0; j < 4; j++) b[j] = sIn[(tx * 4 + j) * PITCH + e];
        #pragma unroll
        for (int i = 0; i < 4; i++)
            #pragma unroll
            for (int j = 0; j < 4; j++)
                acc[i][j] = fmaf(a[i], b[j], acc[i][j]);
    }

    float* ob = out + ((size_t)n * 64 * 512 + f) * 64;
    #pragma unroll
    for (int i = 0; i < 4; i++) {
        float4 v = make_float4(acc[i][0], acc[i][1], acc[i][2], acc[i][3]);
        *(float4*)(ob + (size_t)(ty * 4 + i) * (512 * 64) + tx * 4) = v;
    }
}

// ---------------------------------------------------------------------------
// Kernel 2: attention. grid (4 qtile, 64 e, 8 n), block 128.
// tcgen05 path: S = QK^T via 3x tf32 hi/lo split; P = exp(S/8);
// O += PV via 3x tf32 split; O /= sum(P). S in TMEM 0-63, O in 64-127.
// Fallback path (non-'a' targets): scalar per-row flash attention.
// ---------------------------------------------------------------------------
__global__ void __launch_bounds__(128, 1) attn_tc_kernel()
{
    extern __shared__ char smem[];
    const int tid = threadIdx.x;
    const int qb = blockIdx.x, e = blockIdx.y, n = blockIdx.z;
    const size_t base = (size_t)(n * 64 + e) * 512 * 64;
    const float* Qg = g_Qp + base + (size_t)qb * 128 * 64;
    const float* Kg = g_Kp + base;
    const float* Vg = g_Vp + base;

#if ATTN_TCGEN
    const uint32_t sb = smem_u32(smem);
    const int wid = tid >> 5;

    if (wid == 0) TC_ALLOC(sb + SM_TMEM, 128);
    if (tid == 0) { MBAR_INIT(sb + SM_MB1, 1); MBAR_INIT(sb + SM_MB2, 1); }
    __syncthreads();
    uint32_t tmem;
    asm volatile("ld.shared.b32 %0, [%1];" : "=r"(tmem) : "r"(sb + SM_TMEM));
    const uint32_t tS = tmem, tO = tmem + 64;

    // Load Q tile [128 q][64 t], hi/lo split, SW128 blocked layout
    #pragma unroll 4
    for (int i = tid; i < 2048; i += 128) {
        int r = i >> 4, c4 = (i & 15) << 2;
        float4 v = *(const float4*)(Qg + r * 64 + c4);
        float4 h, l;
        h.x = hi13(v.x); l.x = v.x - h.x;
        h.y = hi13(v.y); l.y = v.y - h.y;
        h.z = hi13(v.z); l.z = v.z - h.z;
        h.w = hi13(v.w); l.w = v.w - h.w;
        uint32_t ac = (uint32_t)(c4 >> 5) * 16384u;
        uint32_t sw = swz((uint32_t)(r * 128 + (c4 & 31) * 4));
        *(float4*)(smem + SM_QHI + ac + sw) = h;
        *(float4*)(smem + SM_QLO + ac + sw) = l;
    }

    const uint64_t dQhi = make_desc(sb + SM_QHI), dQlo = make_desc(sb + SM_QLO);
    const uint64_t dKhi = make_desc(sb + SM_KHI), dKlo = make_desc(sb + SM_KLO);
    const uint64_t dVhi = make_desc(sb + SM_VHI), dVlo = make_desc(sb + SM_VLO);
    const uint64_t dPhi = make_desc(sb + SM_PHI), dPlo = make_desc(sb + SM_PLO);

    float l_sum = 0.0f;
    uint32_t sreg[64];

    for (int kc = 0; kc < 8; kc++) {
        if (kc > 0) MBAR_WAIT(sb + SM_MB2, (kc - 1) & 1);  // prev GEMM2 done

        // Load K chunk (hi/lo) and V chunk (transposed to [t][k], hi/lo)
        const float* Kc = Kg + kc * 64 * 64;
        const float* Vc = Vg + kc * 64 * 64;
        #pragma unroll 2
        for (int i = tid; i < 1024; i += 128) {
            int r = i >> 4, c4 = (i & 15) << 2;
            float4 kv = *(const float4*)(Kc + r * 64 + c4);
            float4 h, l;
            h.x = hi13(kv.x); l.x = kv.x - h.x;
            h.y = hi13(kv.y); l.y = kv.y - h.y;
            h.z = hi13(kv.z); l.z = kv.z - h.z;
            h.w = hi13(kv.w); l.w = kv.w - h.w;
            uint32_t ac = (uint32_t)(c4 >> 5) * 8192u;
            uint32_t sw = swz((uint32_t)(r * 128 + (c4 & 31) * 4));
            *(float4*)(smem + SM_KHI + ac + sw) = h;
            *(float4*)(smem + SM_KLO + ac + sw) = l;

            float4 vv = *(const float4*)(Vc + r * 64 + c4);
            const float* vp = (const float*)&vv;
            uint32_t vac = (uint32_t)(r >> 5) * 8192u;   // k = r selects atom col
            #pragma unroll
            for (int j = 0; j < 4; j++) {
                int t = c4 + j, k = r;
                float vh = hi13(vp[j]);
                uint32_t o2 = swz((uint32_t)(t * 128 + (k & 31) * 4));
                *(float*)(smem + SM_VHI + vac + o2) = vh;
                *(float*)(smem + SM_VLO + vac + o2) = vp[j] - vh;
            }
        }
        FENCE_ASYNC();
        __syncthreads();

        // GEMM1: S = Qhi*Khi + Qhi*Klo + Qlo*Khi
        if (wid == 0) {
            TC_FENCE_AFTER();
            if (elect_one()) {
                #pragma unroll
                for (int pass = 0; pass < 3; pass++) {
                    uint64_t A = (pass == 2) ? dQlo : dQhi;
                    uint64_t B = (pass == 1) ? dKlo : dKhi;
                    #pragma unroll
                    for (int s = 0; s < 8; s++) {
                        uint64_t ao = A + (uint64_t)((s >> 2) * 1024 + (s & 3) * 2);
                        uint64_t bo = B + (uint64_t)((s >> 2) * 512 + (s & 3) * 2);
                        mma_tf32_ss(tS, ao, bo, IDESC_TF32, !(pass == 0 && s == 0));
                    }
                }
                TC_COMMIT(sb + SM_MB1);
            }
        }
        MBAR_WAIT(sb + SM_MB1, kc & 1);
        TC_FENCE_AFTER();

        // Read S row (q = tid), exp, accumulate row sum
        TC_LD_X32(sreg, tS);
        TC_LD_X32(sreg + 32, tS + 32);
        TC_WAIT_LD();
        float l_loc = 0.0f;
        #pragma unroll
        for (int c = 0; c < 64; c++) {
            float sv = __uint_as_float(sreg[c]);
            float pe = __expf(sv * 0.125f);
            sreg[c] = __float_as_uint(pe);
            l_loc += pe;
        }
        l_sum += l_loc;

        // Store P hi/lo rows to smem (128-row tile => atom-col stride 16KB)
        #pragma unroll
        for (int c4 = 0; c4 < 64; c4 += 4) {
            float4 ph, pl;
            float p0 = __uint_as_float(sreg[c4 + 0]);
            float p1 = __uint_as_float(sreg[c4 + 1]);
            float p2 = __uint_as_float(sreg[c4 + 2]);
            float p3 = __uint_as_float(sreg[c4 + 3]);
            ph.x = hi13(p0); pl.x = p0 - ph.x;
            ph.y = hi13(p1); pl.y = p1 - ph.y;
            ph.z = hi13(p2); pl.z = p2 - ph.z;
            ph.w = hi13(p3); pl.w = p3 - ph.w;
            uint32_t ac = (uint32_t)(c4 >> 5) * 16384u;
            uint32_t sw = swz((uint32_t)(tid * 128 + (c4 & 31) * 4));
            *(float4*)(smem + SM_PHI + ac + sw) = ph;
            *(float4*)(smem + SM_PLO + ac + sw) = pl;
        }
        TC_FENCE_BEFORE();
        FENCE_ASYNC();
        __syncthreads();

        // GEMM2: O += Phi*Vhi + Phi*Vlo + Plo*Vhi
        if (wid == 0) {
            TC_FENCE_AFTER();
            if (elect_one()) {
                #pragma unroll
                for (int pass = 0; pass < 3; pass++) {
                    uint64_t A = (pass == 2) ? dPlo : dPhi;
                    uint64_t B = (pass == 1) ? dVlo : dVhi;
                    #pragma unroll
                    for (int s = 0; s < 8; s++) {
                        uint64_t ao = A + (uint64_t)((s >> 2) * 1024 + (s & 3) * 2);
                        uint64_t bo = B + (uint64_t)((s >> 2) * 512 + (s & 3) * 2);
                        mma_tf32_ss(tO, ao, bo, IDESC_TF32,
                                    !(kc == 0 && pass == 0 && s == 0));
                    }
                }
                TC_COMMIT(sb + SM_MB2);
            }
        }
    }

    MBAR_WAIT(sb + SM_MB2, 1);   // 8th commit => parity 1
    TC_FENCE_AFTER();

    TC_LD_X32(sreg, tO);
    TC_LD_X32(sreg + 32, tO + 32);
    TC_WAIT_LD();
    TC_FENCE_BEFORE();

    const float inv = 1.0f / l_sum;
    float* Og = g_Op + base + (size_t)qb * 128 * 64 + (size_t)tid * 64;
    #pragma unroll
    for (int c4 = 0; c4 < 64; c4 += 4) {
        float4 ov = make_float4(__uint_as_float(sreg[c4 + 0]) * inv,
                                __uint_as_float(sreg[c4 + 1]) * inv,
                                __uint_as_float(sreg[c4 + 2]) * inv,
                                __uint_as_float(sreg[c4 + 3]) * inv);
        *(float4*)(Og + c4) = ov;
    }

    __syncthreads();
    if (wid == 0) { TC_RELINQ(); TC_DEALLOC(tmem, 128); }

#else   // ------------------- scalar fallback (non-'a' target) ---------------
    float* sK = (float*)smem;          // [64][65]
    float* sV = sK + 64 * 65;          // [64][65]

    float qreg[64];
    #pragma unroll
    for (int t = 0; t < 64; t++) qreg[t] = Qg[tid * 64 + t];

    float o[64];
    #pragma unroll
    for (int t = 0; t < 64; t++) o[t] = 0.0f;
    float l_sum = 0.0f;

    for (int kc = 0; kc < 8; kc++) {
        __syncthreads();
        #pragma unroll
        for (int i = tid; i < 1024; i += 128) {
            int r = i >> 4, c = (i & 15) * 4;
            size_t off = (size_t)(kc * 64 + r) * 64 + c;
            float4 kv = *(const float4*)(Kg + off);
            float4 vv = *(const float4*)(Vg + off);
            float* dk = &sK[r * 65 + c];
            dk[0] = kv.x; dk[1] = kv.y; dk[2] = kv.z; dk[3] = kv.w;
            float* dv = &sV[r * 65 + c];
            dv[0] = vv.x; dv[1] = vv.y; dv[2] = vv.z; dv[3] = vv.w;
        }
        __syncthreads();

        for (int k = 0; k < 64; k++) {
            float s = 0.0f;
            #pragma unroll 16
            for (int t = 0; t < 64; t++) s = fmaf(qreg[t], sK[k * 65 + t], s);
            float p = __expf(s * 0.125f);
            l_sum += p;
            #pragma unroll 16
            for (int t = 0; t < 64; t++) o[t] = fmaf(p, sV[k * 65 + t], o[t]);
        }
    }

    const float inv = 1.0f / l_sum;
    float* Og = g_Op + base + (size_t)qb * 128 * 64 + (size_t)tid * 64;
    #pragma unroll
    for (int c = 0; c < 64; c++) Og[c] = o[c] * inv;
#endif
}

// ---------------------------------------------------------------------------
// Kernel 3: output projection + transpose back.
// ---------------------------------------------------------------------------
__global__ __launch_bounds__(256) void out_kernel(
    const float* __restrict__ Wo, const float* __restrict__ bo,
    float* __restrict__ out)
{
    __shared__ float sO[64 * PITCH];
    __shared__ float sW[64 * PITCH];
    __shared__ float sb_[64];

    const int q = blockIdx.x, n = blockIdx.y;
    const int tid = threadIdx.x, ty = tid >> 4, tx = tid & 15;

    #pragma unroll
    for (int i = tid; i < 4096; i += 256)
        sW[(i >> 6) * PITCH + (i & 63)] = Wo[i];
    if (tid < 64) sb_[tid] = bo[tid];

    #pragma unroll
    for (int i = tid; i < 1024; i += 256) {
        int er = i >> 4, c = (i & 15) * 4;
        float4 v = *(const float4*)(g_Op + ((size_t)(n * 64 + er) * 512 + q) * 64 + c);
        float* d = &sO[er * PITCH + c];
        d[0] = v.x; d[1] = v.y; d[2] = v.z; d[3] = v.w;
    }
    __syncthreads();

    float acc[4][4] = {};
    #pragma unroll
    for (int e = 0; e < 64; e++) {
        float a[4], b[4];
        #pragma unroll
        for (int i = 0; i < 4; i++) a[i] = sO[e * PITCH + ty * 4 + i];
        #pragma unroll
        for (int j = 0; j < 4; j++) b[j] = sW[(tx * 4 + j) * PITCH + e];
        #pragma unroll
        for (int i = 0; i < 4; i++)
            #pragma unroll
            for (int j = 0; j < 4; j++)
                acc[i][j] = fmaf(a[i], b[j], acc[i][j]);
    }

    #pragma unroll
    for (int i = 0; i < 4; i++) {
        int t = ty * 4 + i;
        float4 v = make_float4(acc[i][0] + sb_[tx * 4 + 0],
                               acc[i][1] + sb_[tx * 4 + 1],
                               acc[i][2] + sb_[tx * 4 + 2],
                               acc[i][3] + sb_[tx * 4 + 3]);
        *(float4*)(out + ((size_t)(n * 64 + t) * 512 + q) * 64 + tx * 4) = v;
    }
}

// ---------------------------------------------------------------------------
extern "C" void kernel_launch(void* const* d_in, const int* in_sizes, int n_in,
                              void* d_out, int out_size)
{
    const float* value = (const float*)d_in[0];
    const float* key   = (const float*)d_in[1];
    const float* query = (const float*)d_in[2];
    const float* Wv    = (const float*)d_in[3];
    const float* Wk    = (const float*)d_in[4];
    const float* Wq    = (const float*)d_in[5];
    const float* Wo    = (const float*)d_in[6];
    const float* bo    = (const float*)d_in[7];
    float* out = (float*)d_out;

    cudaFuncSetAttribute(attn_tc_kernel,
                         cudaFuncAttributeMaxDynamicSharedMemorySize, SM_TOTAL);

    dim3 g1(512, 8, 3);
    proj_kernel<<<g1, 256>>>(query, key, value, Wq, Wk, Wv);

    dim3 g2(4, 64, 8);
    attn_tc_kernel<<<g2, 128, SM_TOTAL>>>();

    dim3 g3(512, 8);
    out_kernel<<<g3, 256>>>(Wo, bo, out);
}

// round 4
// speedup vs baseline: 2.3271x; 1.6246x over previous
#include <cuda_runtime.h>
#include <cuda_bf16.h>
#include <cstdint>
#include <math.h>

// Problem dims: N=8, T=64, F=512, E=64
#define PITCH 65

// Arch-feature gate: tcgen05 exists only on sm_100a/sm_103a ('a' targets).
#if defined(__CUDA_ARCH__) && (defined(__CUDA_ARCH_FEAT_SM103_ALL) || \
    defined(__CUDA_ARCH_FEAT_SM100_ALL) || \
    (defined(__CUDA_ARCH_SPECIFIC__) && (__CUDA_ARCH_SPECIFIC__ >= 1000)))
#define ATTN_TCGEN 1
#else
#define ATTN_TCGEN 0
#endif

#define NELEM (8u * 64u * 512u * 64u)
// Projected Q/K in bf16 hi/lo, layout [n][e][f][t]
__device__ __nv_bfloat16 g_Qhi[NELEM];
__device__ __nv_bfloat16 g_Qlo[NELEM];
__device__ __nv_bfloat16 g_Khi[NELEM];
__device__ __nv_bfloat16 g_Klo[NELEM];
// Projected V fp32 [n][e][f][t] (transpose-kernel input)
__device__ float g_Vp[NELEM];
// V transposed, bf16 hi/lo, layout [n][e][t][f]
__device__ __nv_bfloat16 g_Vthi[NELEM];
__device__ __nv_bfloat16 g_Vtlo[NELEM];
// Attention output fp32 [n][e][q][t]
__device__ float g_Op[NELEM];

// ============================================================================
// PTX helpers
// ============================================================================
__device__ __forceinline__ uint32_t smem_u32(const void* p) {
    uint32_t a;
    asm("{ .reg .u64 t; cvta.to.shared.u64 t, %1; cvt.u32.u64 %0, t; }"
        : "=r"(a) : "l"(p));
    return a;
}
#if ATTN_TCGEN
__device__ __forceinline__ uint32_t elect_one() {
    uint32_t p;
    asm volatile("{\n\t.reg .pred p;\n\telect.sync _|p, 0xFFFFFFFF;\n\t"
                 "selp.b32 %0, 1, 0, p;\n\t}" : "=r"(p));
    return p;
}
#endif
#define MBAR_INIT(a, c) \
    asm volatile("mbarrier.init.shared.b64 [%0], %1;" :: "r"(a), "r"(c) : "memory")
#define MBAR_WAIT(a, ph) do { \
    uint32_t _m = (a), _p = (ph), _d; \
    asm volatile("{\n\t.reg .pred p;\n\t" \
        "mbarrier.try_wait.parity.acquire.cta.shared::cta.b64 p, [%1], %2;\n\t" \
        "selp.b32 %0, 1, 0, p;\n\t}" : "=r"(_d) : "r"(_m), "r"(_p) : "memory"); \
    if (!_d) { \
        asm volatile("{\n\t.reg .pred P1;\n\tWL_%=: \n\t" \
            "mbarrier.try_wait.parity.acquire.cta.shared::cta.b64 P1, [%0], %1, 0x989680;\n\t" \
            "@P1 bra.uni WD_%=;\n\tbra.uni WL_%=;\n\tWD_%=: \n\t}" \
            :: "r"(_m), "r"(_p) : "memory"); \
    } } while (0)

#define TC_ALLOC(sa, n)  asm volatile( \
    "tcgen05.alloc.cta_group::1.sync.aligned.shared::cta.b32 [%0], %1;" \
    :: "r"(sa), "r"(n) : "memory")
#define TC_DEALLOC(t, n) asm volatile( \
    "tcgen05.dealloc.cta_group::1.sync.aligned.b32 %0, %1;" :: "r"(t), "r"(n))
#define TC_RELINQ() asm volatile("tcgen05.relinquish_alloc_permit.cta_group::1.sync.aligned;")
#define TC_COMMIT(mb) asm volatile( \
    "tcgen05.commit.cta_group::1.mbarrier::arrive::one.shared::cluster.b64 [%0];" \
    :: "r"(mb) : "memory")
#define TC_WAIT_LD() asm volatile("tcgen05.wait::ld.sync.aligned;" ::: "memory")
#define TC_FENCE_BEFORE() asm volatile("tcgen05.fence::before_thread_sync;" ::: "memory")
#define TC_FENCE_AFTER()  asm volatile("tcgen05.fence::after_thread_sync;" ::: "memory")
#define FENCE_ASYNC() asm volatile("fence.proxy.async.shared::cta;" ::: "memory")

#define TC_LD_X32(r, ta) asm volatile( \
    "tcgen05.ld.sync.aligned.32x32b.x32.b32 " \
    "{%0,%1,%2,%3,%4,%5,%6,%7,%8,%9,%10,%11,%12,%13,%14,%15," \
    "%16,%17,%18,%19,%20,%21,%22,%23,%24,%25,%26,%27,%28,%29,%30,%31}, [%32];" \
    : "=r"((r)[0]),"=r"((r)[1]),"=r"((r)[2]),"=r"((r)[3]), \
      "=r"((r)[4]),"=r"((r)[5]),"=r"((r)[6]),"=r"((r)[7]), \
      "=r"((r)[8]),"=r"((r)[9]),"=r"((r)[10]),"=r"((r)[11]), \
      "=r"((r)[12]),"=r"((r)[13]),"=r"((r)[14]),"=r"((r)[15]), \
      "=r"((r)[16]),"=r"((r)[17]),"=r"((r)[18]),"=r"((r)[19]), \
      "=r"((r)[20]),"=r"((r)[21]),"=r"((r)[22]),"=r"((r)[23]), \
      "=r"((r)[24]),"=r"((r)[25]),"=r"((r)[26]),"=r"((r)[27]), \
      "=r"((r)[28]),"=r"((r)[29]),"=r"((r)[30]),"=r"((r)[31]) \
    : "r"(ta))

#if ATTN_TCGEN
__device__ __forceinline__ void mma_bf16_ss(uint32_t d, uint64_t a, uint64_t b,
                                            uint32_t idesc, bool en) {
    uint32_t e = en ? 1u : 0u;
    asm volatile(
        "{\n\t.reg .pred p;\n\tsetp.ne.u32 p, %5, 0;\n\t"
        "tcgen05.mma.cta_group::1.kind::f16 [%0], %1, %2, %3, {%4,%4,%4,%4}, p;\n\t}"
        :: "r"(d), "l"(a), "l"(b), "r"(idesc), "r"(0u), "r"(e) : "memory");
}
#endif

// SMEM desc: SW128, version=1(Blackwell), SBO=64, LBO=1
static __device__ __forceinline__ uint64_t make_desc(uint32_t addr) {
    const uint64_t base = (uint64_t(2) << 61) | (uint64_t(1) << 46) |
                          (uint64_t(64) << 32) | (uint64_t(1) << 16);
    return base | ((uint64_t)(addr >> 4) & 0x3FFF);
}

// idesc kind::f16 bf16: dtype=F32(1<<4), atype=BF16(1<<7), btype=BF16(1<<10),
// N=64 ((64/8)<<17), M=128 ((128/16)<<24)
#define IDESC_BF16 ((1u<<4) | (1u<<7) | (1u<<10) | (8u<<17) | (8u<<24))

// smem layout (bytes); bf16 tiles have 128B rows (one SW128 atom column)
#define SM_TMEM 0
#define SM_MB1  16
#define SM_MB2  24
#define SM_QHI  1024
#define SM_QLO  (SM_QHI + 16384)   // 17408
#define SM_PHI  (SM_QLO + 16384)   // 33792
#define SM_PLO  (SM_PHI + 16384)   // 50176
#define SM_K    (SM_PLO + 16384)   // 66560: [buf]{hi 8KB, lo 8KB} x2
#define SM_V    (SM_K + 32768)     // 99328: [buf]{hi 8KB, lo 8KB} x2
#define SM_TOTAL (SM_V + 32768 + 128)  // 132224

__device__ __forceinline__ uint32_t swz(uint32_t off) {
    return off ^ ((off >> 3) & 0x70);
}

// ---------------------------------------------------------------------------
// Kernel 1: projection. Q/K -> bf16 hi/lo [n][e][f][t]; V -> fp32 [n][e][f][t].
// grid (512 f, 8 n, 3 which), block 256.
// ---------------------------------------------------------------------------
__global__ __launch_bounds__(256) void proj_kernel(
    const float* __restrict__ qin, const float* __restrict__ kin,
    const float* __restrict__ vin, const float* __restrict__ Wq,
    const float* __restrict__ Wk, const float* __restrict__ Wv)
{
    __shared__ float sW[64 * PITCH];
    __shared__ float sIn[64 * PITCH];

    const int f = blockIdx.x, n = blockIdx.y, w = blockIdx.z;
    const float* in; const float* W;
    if (w == 0)      { in = qin; W = Wq; }
    else if (w == 1) { in = kin; W = Wk; }
    else             { in = vin; W = Wv; }

    const int tid = threadIdx.x;
    #pragma unroll
    for (int i = tid; i < 4096; i += 256)
        sW[(i >> 6) * PITCH + (i & 63)] = W[i];

    const float* inb = in + ((size_t)n * 64 * 512 + f) * 64;
    #pragma unroll
    for (int i = tid; i < 1024; i += 256) {
        int t = i >> 4, c = (i & 15) * 4;
        float4 v = *(const float4*)(inb + (size_t)t * (512 * 64) + c);
        float* d = &sIn[t * PITCH + c];
        d[0] = v.x; d[1] = v.y; d[2] = v.z; d[3] = v.w;
    }
    __syncthreads();

    const int ty = tid >> 4, tx = tid & 15;
    float acc[4][4] = {};
    #pragma unroll
    for (int e = 0; e < 64; e++) {
        float a[4], b[4];
        #pragma unroll
        for (int i = 0; i < 4; i++) a[i] = sW[(ty * 4 + i) * PITCH + e];
        #pragma unroll
        for (int j = 0; j < 4; j++) b[j] = sIn[(tx * 4 + j) * PITCH + e];
        #pragma unroll
        for (int i = 0; i < 4; i++)
            #pragma unroll
            for (int j = 0; j < 4; j++)
                acc[i][j] = fmaf(a[i], b[j], acc[i][j]);
    }

    if (w < 2) {
        __nv_bfloat16* ohi = (w == 0) ? g_Qhi : g_Khi;
        __nv_bfloat16* olo = (w == 0) ? g_Qlo : g_Klo;
        #pragma unroll
        for (int i = 0; i < 4; i++) {
            int d = ty * 4 + i;
            size_t off = (((size_t)n * 64 + d) * 512 + f) * 64 + tx * 4;
            __nv_bfloat162 h01, h23, l01, l23;
            float v0 = acc[i][0], v1 = acc[i][1], v2 = acc[i][2], v3 = acc[i][3];
            __nv_bfloat16 h0 = __float2bfloat16(v0), h1 = __float2bfloat16(v1);
            __nv_bfloat16 h2 = __float2bfloat16(v2), h3 = __float2bfloat16(v3);
            h01.x = h0; h01.y = h1; h23.x = h2; h23.y = h3;
            l01.x = __float2bfloat16(v0 - __bfloat162float(h0));
            l01.y = __float2bfloat16(v1 - __bfloat162float(h1));
            l23.x = __float2bfloat16(v2 - __bfloat162float(h2));
            l23.y = __float2bfloat16(v3 - __bfloat162float(h3));
            uint2 hp, lp;
            hp.x = *(uint32_t*)&h01; hp.y = *(uint32_t*)&h23;
            lp.x = *(uint32_t*)&l01; lp.y = *(uint32_t*)&l23;
            *(uint2*)(ohi + off) = hp;
            *(uint2*)(olo + off) = lp;
        }
    } else {
        float* ob = g_Vp + ((size_t)n * 64 * 512 + f) * 64;
        #pragma unroll
        for (int i = 0; i < 4; i++) {
            float4 v = make_float4(acc[i][0], acc[i][1], acc[i][2], acc[i][3]);
            *(float4*)(ob + (size_t)(ty * 4 + i) * (512 * 64) + tx * 4) = v;
        }
    }
}

// ---------------------------------------------------------------------------
// Kernel 1b: V transpose + bf16 split. [n][e][f][t] fp32 -> [n][e][t][f] bf16 x2
// grid (8 fblk, 64 e, 8 n), block 256.
// ---------------------------------------------------------------------------
__global__ __launch_bounds__(256) void vtrans_kernel()
{
    __shared__ float sT[64 * PITCH];
    const int fb = blockIdx.x, e = blockIdx.y, n = blockIdx.z;
    const int tid = threadIdx.x;

    const float* src = g_Vp + ((size_t)(n * 64 + e) * 512 + fb * 64) * 64;
    #pragma unroll
    for (int j = 0; j < 4; j++) {
        int idx = tid + j * 256;                 // 0..1023 float4 units
        int r = idx >> 4, c = (idx & 15) * 4;    // r = f-local, c = t
        float4 v = *(const float4*)(src + (size_t)r * 64 + c);
        float* d = &sT[r * PITCH + c];
        d[0] = v.x; d[1] = v.y; d[2] = v.z; d[3] = v.w;
    }
    __syncthreads();

    __nv_bfloat16* dh = g_Vthi + (size_t)(n * 64 + e) * 64 * 512 + fb * 64;
    __nv_bfloat16* dl = g_Vtlo + (size_t)(n * 64 + e) * 64 * 512 + fb * 64;
    #pragma unroll
    for (int j = 0; j < 4; j++) {
        int idx = tid + j * 256;                 // (t, f4) units
        int t = idx >> 4, f4 = (idx & 15) * 4;
        float v0 = sT[(f4 + 0) * PITCH + t];
        float v1 = sT[(f4 + 1) * PITCH + t];
        float v2 = sT[(f4 + 2) * PITCH + t];
        float v3 = sT[(f4 + 3) * PITCH + t];
        __nv_bfloat16 h0 = __float2bfloat16(v0), h1 = __float2bfloat16(v1);
        __nv_bfloat16 h2 = __float2bfloat16(v2), h3 = __float2bfloat16(v3);
        __nv_bfloat162 h01, h23, l01, l23;
        h01.x = h0; h01.y = h1; h23.x = h2; h23.y = h3;
        l01.x = __float2bfloat16(v0 - __bfloat162float(h0));
        l01.y = __float2bfloat16(v1 - __bfloat162float(h1));
        l23.x = __float2bfloat16(v2 - __bfloat162float(h2));
        l23.y = __float2bfloat16(v3 - __bfloat162float(h3));
        uint2 hp, lp;
        hp.x = *(uint32_t*)&h01; hp.y = *(uint32_t*)&h23;
        lp.x = *(uint32_t*)&l01; lp.y = *(uint32_t*)&l23;
        *(uint2*)(dh + (size_t)t * 512 + f4) = hp;
        *(uint2*)(dl + (size_t)t * 512 + f4) = lp;
    }
}

#if ATTN_TCGEN
// Load one K/V chunk (bf16 hi/lo) into smem buffer b. 16 LDG.128 + 16 STS.128.
__device__ __forceinline__ void load_kv_chunk(
    char* smem, const __nv_bfloat16* Khg, const __nv_bfloat16* Klg,
    const __nv_bfloat16* Vhg, const __nv_bfloat16* Vlg,
    int c, int b, int tid)
{
    const __nv_bfloat16* kh = Khg + c * 64 * 64;
    const __nv_bfloat16* kl = Klg + c * 64 * 64;
    char* kbase = smem + SM_K + b * 16384;
    char* vbase = smem + SM_V + b * 16384;
    #pragma unroll
    for (int j = 0; j < 4; j++) {
        int idx = tid + j * 128;            // 0..511 16B units
        int r = idx >> 3, c16 = idx & 7;
        uint32_t sw = swz((uint32_t)(r * 128 + c16 * 16));
        uint4 a  = *(const uint4*)(kh + r * 64 + c16 * 8);
        uint4 bb = *(const uint4*)(kl + r * 64 + c16 * 8);
        *(uint4*)(kbase + sw) = a;
        *(uint4*)(kbase + 8192 + sw) = bb;
        uint4 vh = *(const uint4*)(Vhg + (size_t)r * 512 + c * 64 + c16 * 8);
        uint4 vl = *(const uint4*)(Vlg + (size_t)r * 512 + c * 64 + c16 * 8);
        *(uint4*)(vbase + sw) = vh;
        *(uint4*)(vbase + 8192 + sw) = vl;
    }
}

// 3-pass split GEMM: (Ahi,Bhi) + (Ahi,Blo) + (Alo,Bhi). 12 dispatches.
__device__ __forceinline__ void issue_3pass(uint32_t dst, uint64_t ahi, uint64_t alo,
                                            uint64_t bhi, uint64_t blo, bool accum)
{
    #pragma unroll
    for (int p = 0; p < 3; p++) {
        uint64_t A = (p == 2) ? alo : ahi;
        uint64_t B = (p == 1) ? blo : bhi;
        #pragma unroll
        for (int s = 0; s < 4; s++)
            mma_bf16_ss(dst, A + s * 2, B + s * 2, IDESC_BF16,
                        accum || !(p == 0 && s == 0));
    }
}
#endif

// ---------------------------------------------------------------------------
// Kernel 2: attention. grid (4 qtile, 64 e, 8 n), block 128.
// bf16x2-split tcgen05 GEMMs, double-buffered K/V, softmax w/o max-subtract.
// ---------------------------------------------------------------------------
__global__ void __launch_bounds__(128, 1) attn_tc_kernel()
{
    extern __shared__ char smem[];
    const int tid = threadIdx.x;
    const int qb = blockIdx.x, e = blockIdx.y, n = blockIdx.z;
    const size_t plane = (size_t)(n * 64 + e);
    const size_t qk_base = plane * 512 * 64;   // [f][t]
    const __nv_bfloat16* Qhg = g_Qhi + qk_base + (size_t)qb * 128 * 64;
    const __nv_bfloat16* Qlg = g_Qlo + qk_base + (size_t)qb * 128 * 64;
    const __nv_bfloat16* Khg = g_Khi + qk_base;
    const __nv_bfloat16* Klg = g_Klo + qk_base;
    const __nv_bfloat16* Vhg = g_Vthi + plane * 64 * 512;  // [t][f]
    const __nv_bfloat16* Vlg = g_Vtlo + plane * 64 * 512;

#if ATTN_TCGEN
    const uint32_t sb = smem_u32(smem);
    const int wid = tid >> 5;

    if (wid == 0) TC_ALLOC(sb + SM_TMEM, 128);
    if (tid == 0) { MBAR_INIT(sb + SM_MB1, 1); MBAR_INIT(sb + SM_MB2, 1); }
    __syncthreads();
    uint32_t tmem;
    asm volatile("ld.shared.b32 %0, [%1];" : "=r"(tmem) : "r"(sb + SM_TMEM));
    const uint32_t tS = tmem, tO = tmem + 64;

    // Prologue: Q tiles + chunk 0 of K/V
    #pragma unroll
    for (int j = 0; j < 8; j++) {
        int idx = tid + j * 128;          // 0..1023 16B units
        int r = idx >> 3, c16 = idx & 7;
        uint32_t sw = swz((uint32_t)(r * 128 + c16 * 16));
        uint4 qh = *(const uint4*)(Qhg + r * 64 + c16 * 8);
        uint4 ql = *(const uint4*)(Qlg + r * 64 + c16 * 8);
        *(uint4*)(smem + SM_QHI + sw) = qh;
        *(uint4*)(smem + SM_QLO + sw) = ql;
    }
    load_kv_chunk(smem, Khg, Klg, Vhg, Vlg, 0, 0, tid);
    FENCE_ASYNC();
    TC_FENCE_BEFORE();
    __syncthreads();

    const uint64_t dQh = make_desc(sb + SM_QHI), dQl = make_desc(sb + SM_QLO);
    const uint64_t dPh = make_desc(sb + SM_PHI), dPl = make_desc(sb + SM_PLO);
    uint64_t dKh[2], dKl[2], dVh[2], dVl[2];
    #pragma unroll
    for (int b = 0; b < 2; b++) {
        dKh[b] = make_desc(sb + SM_K + b * 16384);
        dKl[b] = make_desc(sb + SM_K + b * 16384 + 8192);
        dVh[b] = make_desc(sb + SM_V + b * 16384);
        dVl[b] = make_desc(sb + SM_V + b * 16384 + 8192);
    }

    // GEMM1(0)
    if (wid == 0) {
        TC_FENCE_AFTER();
        if (elect_one()) {
            issue_3pass(tS, dQh, dQl, dKh[0], dKl[0], false);
            TC_COMMIT(sb + SM_MB1);
        }
    }

    float l_sum = 0.0f;
    uint32_t sreg[64];

    for (int kc = 0; kc < 8; kc++) {
        // V/P buffers freed by GEMM2(kc-1)
        if (kc > 0) MBAR_WAIT(sb + SM_MB2, (kc - 1) & 1);
        // prefetch next chunk (overlaps GEMM1(kc))
        if (kc < 7) load_kv_chunk(smem, Khg, Klg, Vhg, Vlg, kc + 1, (kc + 1) & 1, tid);

        // S ready
        MBAR_WAIT(sb + SM_MB1, kc & 1);
        TC_FENCE_AFTER();
        TC_LD_X32(sreg, tS);
        TC_LD_X32(sreg + 32, tS + 32);
        TC_WAIT_LD();

        float l_loc = 0.0f;
        #pragma unroll
        for (int c = 0; c < 64; c++) {
            float sv = __uint_as_float(sreg[c]);
            float pe = __expf(sv * 0.125f);
            sreg[c] = __float_as_uint(pe);
            l_loc += pe;
        }
        l_sum += l_loc;

        // pack P row (q = tid) to bf16 hi/lo, swizzled 16B stores
        #pragma unroll
        for (int g = 0; g < 8; g++) {
            uint32_t hw[4], lw[4];
            #pragma unroll
            for (int x = 0; x < 4; x++) {
                float p0 = __uint_as_float(sreg[g * 8 + x * 2]);
                float p1 = __uint_as_float(sreg[g * 8 + x * 2 + 1]);
                __nv_bfloat16 h0 = __float2bfloat16(p0);
                __nv_bfloat16 h1 = __float2bfloat16(p1);
                __nv_bfloat162 hh, ll;
                hh.x = h0; hh.y = h1;
                ll.x = __float2bfloat16(p0 - __bfloat162float(h0));
                ll.y = __float2bfloat16(p1 - __bfloat162float(h1));
                hw[x] = *(uint32_t*)&hh;
                lw[x] = *(uint32_t*)&ll;
            }
            uint32_t sw = swz((uint32_t)(tid * 128 + g * 16));
            *(uint4*)(smem + SM_PHI + sw) = make_uint4(hw[0], hw[1], hw[2], hw[3]);
            *(uint4*)(smem + SM_PLO + sw) = make_uint4(lw[0], lw[1], lw[2], lw[3]);
        }
        TC_FENCE_BEFORE();
        FENCE_ASYNC();
        __syncthreads();

        if (wid == 0) {
            TC_FENCE_AFTER();
            if (elect_one()) {
                // GEMM2(kc): O += P * V^T (accumulate across chunks)
                issue_3pass(tO, dPh, dPl, dVh[kc & 1], dVl[kc & 1], kc > 0);
                TC_COMMIT(sb + SM_MB2);
                if (kc < 7) {
                    // GEMM1(kc+1): S = Q * K^T (overwrite)
                    issue_3pass(tS, dQh, dQl, dKh[(kc + 1) & 1], dKl[(kc + 1) & 1], false);
                    TC_COMMIT(sb + SM_MB1);
                }
            }
        }
    }

    MBAR_WAIT(sb + SM_MB2, 1);   // 8th GEMM2 commit => parity 1
    TC_FENCE_AFTER();

    TC_LD_X32(sreg, tO);
    TC_LD_X32(sreg + 32, tO + 32);
    TC_WAIT_LD();
    TC_FENCE_BEFORE();

    const float inv = 1.0f / l_sum;
    float* Og = g_Op + plane * 512 * 64 + (size_t)qb * 128 * 64 + (size_t)tid * 64;
    #pragma unroll
    for (int c4 = 0; c4 < 64; c4 += 4) {
        float4 ov = make_float4(__uint_as_float(sreg[c4 + 0]) * inv,
                                __uint_as_float(sreg[c4 + 1]) * inv,
                                __uint_as_float(sreg[c4 + 2]) * inv,
                                __uint_as_float(sreg[c4 + 3]) * inv);
        *(float4*)(Og + c4) = ov;
    }

    __syncthreads();
    if (wid == 0) { TC_RELINQ(); TC_DEALLOC(tmem, 128); }

#else   // ------------------- scalar fallback (non-'a' target) ---------------
    float* sK = (float*)smem;          // [64][65]
    float* sV = sK + 64 * 65;          // [64][65]

    float qreg[64];
    #pragma unroll
    for (int t = 0; t < 64; t++)
        qreg[t] = __bfloat162float(Qhg[tid * 64 + t]) +
                  __bfloat162float(Qlg[tid * 64 + t]);

    float o[64];
    #pragma unroll
    for (int t = 0; t < 64; t++) o[t] = 0.0f;
    float l_sum = 0.0f;
    const float* Vg = g_Vp + plane * 512 * 64;

    for (int kc = 0; kc < 8; kc++) {
        __syncthreads();
        #pragma unroll
        for (int i = tid; i < 1024; i += 128) {
            int r = i >> 4, c = (i & 15) * 4;
            size_t off = (size_t)(kc * 64 + r) * 64 + c;
            #pragma unroll
            for (int j = 0; j < 4; j++)
                sK[r * 65 + c + j] = __bfloat162float(Khg[off + j]) +
                                     __bfloat162float(Klg[off + j]);
            float4 vv = *(const float4*)(Vg + off);
            float* dv = &sV[r * 65 + c];
            dv[0] = vv.x; dv[1] = vv.y; dv[2] = vv.z; dv[3] = vv.w;
        }
        __syncthreads();

        for (int k = 0; k < 64; k++) {
            float s = 0.0f;
            #pragma unroll 16
            for (int t = 0; t < 64; t++) s = fmaf(qreg[t], sK[k * 65 + t], s);
            float p = __expf(s * 0.125f);
            l_sum += p;
            #pragma unroll 16
            for (int t = 0; t < 64; t++) o[t] = fmaf(p, sV[k * 65 + t], o[t]);
        }
    }

    const float inv = 1.0f / l_sum;
    float* Og = g_Op + plane * 512 * 64 + (size_t)qb * 128 * 64 + (size_t)tid * 64;
    #pragma unroll
    for (int c = 0; c < 64; c++) Og[c] = o[c] * inv;
#endif
}

// ---------------------------------------------------------------------------
// Kernel 3: output projection + transpose back.
// ---------------------------------------------------------------------------
__global__ __launch_bounds__(256) void out_kernel(
    const float* __restrict__ Wo, const float* __restrict__ bo,
    float* __restrict__ out)
{
    __shared__ float sO[64 * PITCH];
    __shared__ float sW[64 * PITCH];
    __shared__ float sb_[64];

    const int q = blockIdx.x, n = blockIdx.y;
    const int tid = threadIdx.x, ty = tid >> 4, tx = tid & 15;

    #pragma unroll
    for (int i = tid; i < 4096; i += 256)
        sW[(i >> 6) * PITCH + (i & 63)] = Wo[i];
    if (tid < 64) sb_[tid] = bo[tid];

    #pragma unroll
    for (int i = tid; i < 1024; i += 256) {
        int er = i >> 4, c = (i & 15) * 4;
        float4 v = *(const float4*)(g_Op + ((size_t)(n * 64 + er) * 512 + q) * 64 + c);
        float* d = &sO[er * PITCH + c];
        d[0] = v.x; d[1] = v.y; d[2] = v.z; d[3] = v.w;
    }
    __syncthreads();

    float acc[4][4] = {};
    #pragma unroll
    for (int e = 0; e < 64; e++) {
        float a[4], b[4];
        #pragma unroll
        for (int i = 0; i < 4; i++) a[i] = sO[e * PITCH + ty * 4 + i];
        #pragma unroll
        for (int j = 0; j < 4; j++) b[j] = sW[(tx * 4 + j) * PITCH + e];
        #pragma unroll
        for (int i = 0; i < 4; i++)
            #pragma unroll
            for (int j = 0; j < 4; j++)
                acc[i][j] = fmaf(a[i], b[j], acc[i][j]);
    }

    #pragma unroll
    for (int i = 0; i < 4; i++) {
        int t = ty * 4 + i;
        float4 v = make_float4(acc[i][0] + sb_[tx * 4 + 0],
                               acc[i][1] + sb_[tx * 4 + 1],
                               acc[i][2] + sb_[tx * 4 + 2],
                               acc[i][3] + sb_[tx * 4 + 3]);
        *(float4*)(out + ((size_t)(n * 64 + t) * 512 + q) * 64 + tx * 4) = v;
    }
}

// ---------------------------------------------------------------------------
extern "C" void kernel_launch(void* const* d_in, const int* in_sizes, int n_in,
                              void* d_out, int out_size)
{
    const float* value = (const float*)d_in[0];
    const float* key   = (const float*)d_in[1];
    const float* query = (const float*)d_in[2];
    const float* Wv    = (const float*)d_in[3];
    const float* Wk    = (const float*)d_in[4];
    const float* Wq    = (const float*)d_in[5];
    const float* Wo    = (const float*)d_in[6];
    const float* bo    = (const float*)d_in[7];
    float* out = (float*)d_out;

    cudaFuncSetAttribute(attn_tc_kernel,
                         cudaFuncAttributeMaxDynamicSharedMemorySize, SM_TOTAL);

    dim3 g1(512, 8, 3);
    proj_kernel<<<g1, 256>>>(query, key, value, Wq, Wk, Wv);

    dim3 g1b(8, 64, 8);
    vtrans_kernel<<<g1b, 256>>>();

    dim3 g2(4, 64, 8);
    attn_tc_kernel<<<g2, 128, SM_TOTAL>>>();

    dim3 g3(512, 8);
    out_kernel<<<g3, 256>>>(Wo, bo, out);
}

// round 6
// speedup vs baseline: 2.4069x; 1.0343x over previous
#include <cuda_runtime.h>
#include <cuda_bf16.h>
#include <cstdint>
#include <math.h>

// Problem dims: N=8, T=64, F=512, E=64
#define PITCH 65

// Arch-feature gate: tcgen05 exists only on sm_100a/sm_103a ('a' targets).
#if defined(__CUDA_ARCH__) && (defined(__CUDA_ARCH_FEAT_SM103_ALL) || \
    defined(__CUDA_ARCH_FEAT_SM100_ALL) || \
    (defined(__CUDA_ARCH_SPECIFIC__) && (__CUDA_ARCH_SPECIFIC__ >= 1000)))
#define ATTN_TCGEN 1
#else
#define ATTN_TCGEN 0
#endif

#define NELEM (8u * 64u * 512u * 64u)
// Projected Q/K in bf16 hi/lo, layout [n][e][f][t]
__device__ __nv_bfloat16 g_Qhi[NELEM];
__device__ __nv_bfloat16 g_Qlo[NELEM];
__device__ __nv_bfloat16 g_Khi[NELEM];
__device__ __nv_bfloat16 g_Klo[NELEM];
// Projected V fp32 [n][e][f][t] (transpose-kernel input)
__device__ float g_Vp[NELEM];
// V transposed, bf16 hi/lo, layout [n][e][t][f]
__device__ __nv_bfloat16 g_Vthi[NELEM];
__device__ __nv_bfloat16 g_Vtlo[NELEM];
// Attention output fp32 [n][e][q][t]
__device__ float g_Op[NELEM];

// ============================================================================
// PTX helpers
// ============================================================================
__device__ __forceinline__ uint32_t smem_u32(const void* p) {
    uint32_t a;
    asm("{ .reg .u64 t; cvta.to.shared.u64 t, %1; cvt.u32.u64 %0, t; }"
        : "=r"(a) : "l"(p));
    return a;
}
#if ATTN_TCGEN
__device__ __forceinline__ uint32_t elect_one() {
    uint32_t p;
    asm volatile("{\n\t.reg .pred p;\n\telect.sync _|p, 0xFFFFFFFF;\n\t"
                 "selp.b32 %0, 1, 0, p;\n\t}" : "=r"(p));
    return p;
}
#endif
#define MBAR_INIT(a, c) \
    asm volatile("mbarrier.init.shared.b64 [%0], %1;" :: "r"(a), "r"(c) : "memory")
#define MBAR_WAIT(a, ph) do { \
    uint32_t _m = (a), _p = (ph), _d; \
    asm volatile("{\n\t.reg .pred p;\n\t" \
        "mbarrier.try_wait.parity.acquire.cta.shared::cta.b64 p, [%1], %2;\n\t" \
        "selp.b32 %0, 1, 0, p;\n\t}" : "=r"(_d) : "r"(_m), "r"(_p) : "memory"); \
    if (!_d) { \
        asm volatile("{\n\t.reg .pred P1;\n\tWL_%=: \n\t" \
            "mbarrier.try_wait.parity.acquire.cta.shared::cta.b64 P1, [%0], %1, 0x989680;\n\t" \
            "@P1 bra.uni WD_%=;\n\tbra.uni WL_%=;\n\tWD_%=: \n\t}" \
            :: "r"(_m), "r"(_p) : "memory"); \
    } } while (0)

#define TC_ALLOC(sa, n)  asm volatile( \
    "tcgen05.alloc.cta_group::1.sync.aligned.shared::cta.b32 [%0], %1;" \
    :: "r"(sa), "r"(n) : "memory")
#define TC_DEALLOC(t, n) asm volatile( \
    "tcgen05.dealloc.cta_group::1.sync.aligned.b32 %0, %1;" :: "r"(t), "r"(n))
#define TC_RELINQ() asm volatile("tcgen05.relinquish_alloc_permit.cta_group::1.sync.aligned;")
#define TC_COMMIT(mb) asm volatile( \
    "tcgen05.commit.cta_group::1.mbarrier::arrive::one.shared::cluster.b64 [%0];" \
    :: "r"(mb) : "memory")
#define TC_WAIT_LD() asm volatile("tcgen05.wait::ld.sync.aligned;" ::: "memory")
#define TC_FENCE_BEFORE() asm volatile("tcgen05.fence::before_thread_sync;" ::: "memory")
#define TC_FENCE_AFTER()  asm volatile("tcgen05.fence::after_thread_sync;" ::: "memory")
#define FENCE_ASYNC() asm volatile("fence.proxy.async.shared::cta;" ::: "memory")

#define TC_LD_X32(r, ta) asm volatile( \
    "tcgen05.ld.sync.aligned.32x32b.x32.b32 " \
    "{%0,%1,%2,%3,%4,%5,%6,%7,%8,%9,%10,%11,%12,%13,%14,%15," \
    "%16,%17,%18,%19,%20,%21,%22,%23,%24,%25,%26,%27,%28,%29,%30,%31}, [%32];" \
    : "=r"((r)[0]),"=r"((r)[1]),"=r"((r)[2]),"=r"((r)[3]), \
      "=r"((r)[4]),"=r"((r)[5]),"=r"((r)[6]),"=r"((r)[7]), \
      "=r"((r)[8]),"=r"((r)[9]),"=r"((r)[10]),"=r"((r)[11]), \
      "=r"((r)[12]),"=r"((r)[13]),"=r"((r)[14]),"=r"((r)[15]), \
      "=r"((r)[16]),"=r"((r)[17]),"=r"((r)[18]),"=r"((r)[19]), \
      "=r"((r)[20]),"=r"((r)[21]),"=r"((r)[22]),"=r"((r)[23]), \
      "=r"((r)[24]),"=r"((r)[25]),"=r"((r)[26]),"=r"((r)[27]), \
      "=r"((r)[28]),"=r"((r)[29]),"=r"((r)[30]),"=r"((r)[31]) \
    : "r"(ta))

#if ATTN_TCGEN
__device__ __forceinline__ void mma_bf16_ss(uint32_t d, uint64_t a, uint64_t b,
                                            uint32_t idesc, bool en) {
    uint32_t e = en ? 1u : 0u;
    asm volatile(
        "{\n\t.reg .pred p;\n\tsetp.ne.u32 p, %5, 0;\n\t"
        "tcgen05.mma.cta_group::1.kind::f16 [%0], %1, %2, %3, {%4,%4,%4,%4}, p;\n\t}"
        :: "r"(d), "l"(a), "l"(b), "r"(idesc), "r"(0u), "r"(e) : "memory");
}
#endif

// SMEM desc: SW128, version=1(Blackwell), SBO=64, LBO=1
static __device__ __forceinline__ uint64_t make_desc(uint32_t addr) {
    const uint64_t base = (uint64_t(2) << 61) | (uint64_t(1) << 46) |
                          (uint64_t(64) << 32) | (uint64_t(1) << 16);
    return base | ((uint64_t)(addr >> 4) & 0x3FFF);
}

// idesc kind::f16 bf16: dtype=F32(1<<4), atype=BF16(1<<7), btype=BF16(1<<10),
// N=64 ((64/8)<<17), M=128 ((128/16)<<24)
#define IDESC_BF16 ((1u<<4) | (1u<<7) | (1u<<10) | (8u<<17) | (8u<<24))

// smem layout (bytes); bf16 tiles have 128B rows (one SW128 atom column)
#define SM_TMEM 0
#define SM_MBS0 16     // S-ready barrier, ping buffer
#define SM_MBS1 24     // S-ready barrier, pong buffer
#define SM_MB2  32     // GEMM2-done barrier
#define SM_QHI  1024
#define SM_QLO  (SM_QHI + 16384)
#define SM_PHI  (SM_QLO + 16384)
#define SM_PLO  (SM_PHI + 16384)
#define SM_K    (SM_PLO + 16384)   // [buf]{hi 8KB, lo 8KB} x2
#define SM_V    (SM_K + 32768)
#define SM_RED  (SM_V + 32768)     // 256-float reduction buffer
#define SM_TOTAL (SM_RED + 1024 + 128)

__device__ __forceinline__ uint32_t swz(uint32_t off) {
    return off ^ ((off >> 3) & 0x70);
}

// ---------------------------------------------------------------------------
// Kernel 1: projection. Q/K -> bf16 hi/lo [n][e][f][t]; V -> fp32 [n][e][f][t].
// ---------------------------------------------------------------------------
__global__ __launch_bounds__(256) void proj_kernel(
    const float* __restrict__ qin, const float* __restrict__ kin,
    const float* __restrict__ vin, const float* __restrict__ Wq,
    const float* __restrict__ Wk, const float* __restrict__ Wv)
{
    __shared__ float sW[64 * PITCH];
    __shared__ float sIn[64 * PITCH];

    const int f = blockIdx.x, n = blockIdx.y, w = blockIdx.z;
    const float* in; const float* W;
    if (w == 0)      { in = qin; W = Wq; }
    else if (w == 1) { in = kin; W = Wk; }
    else             { in = vin; W = Wv; }

    const int tid = threadIdx.x;
    #pragma unroll
    for (int i = tid; i < 4096; i += 256)
        sW[(i >> 6) * PITCH + (i & 63)] = W[i];

    const float* inb = in + ((size_t)n * 64 * 512 + f) * 64;
    #pragma unroll
    for (int i = tid; i < 1024; i += 256) {
        int t = i >> 4, c = (i & 15) * 4;
        float4 v = *(const float4*)(inb + (size_t)t * (512 * 64) + c);
        float* d = &sIn[t * PITCH + c];
        d[0] = v.x; d[1] = v.y; d[2] = v.z; d[3] = v.w;
    }
    __syncthreads();

    const int ty = tid >> 4, tx = tid & 15;
    float acc[4][4] = {};
    #pragma unroll
    for (int e = 0; e < 64; e++) {
        float a[4], b[4];
        #pragma unroll
        for (int i = 0; i < 4; i++) a[i] = sW[(ty * 4 + i) * PITCH + e];
        #pragma unroll
        for (int j = 0; j < 4; j++) b[j] = sIn[(tx * 4 + j) * PITCH + e];
        #pragma unroll
        for (int i = 0; i < 4; i++)
            #pragma unroll
            for (int j = 0; j < 4; j++)
                acc[i][j] = fmaf(a[i], b[j], acc[i][j]);
    }

    if (w < 2) {
        __nv_bfloat16* ohi = (w == 0) ? g_Qhi : g_Khi;
        __nv_bfloat16* olo = (w == 0) ? g_Qlo : g_Klo;
        #pragma unroll
        for (int i = 0; i < 4; i++) {
            int d = ty * 4 + i;
            size_t off = (((size_t)n * 64 + d) * 512 + f) * 64 + tx * 4;
            __nv_bfloat162 h01, h23, l01, l23;
            float v0 = acc[i][0], v1 = acc[i][1], v2 = acc[i][2], v3 = acc[i][3];
            __nv_bfloat16 h0 = __float2bfloat16(v0), h1 = __float2bfloat16(v1);
            __nv_bfloat16 h2 = __float2bfloat16(v2), h3 = __float2bfloat16(v3);
            h01.x = h0; h01.y = h1; h23.x = h2; h23.y = h3;
            l01.x = __float2bfloat16(v0 - __bfloat162float(h0));
            l01.y = __float2bfloat16(v1 - __bfloat162float(h1));
            l23.x = __float2bfloat16(v2 - __bfloat162float(h2));
            l23.y = __float2bfloat16(v3 - __bfloat162float(h3));
            uint2 hp, lp;
            hp.x = *(uint32_t*)&h01; hp.y = *(uint32_t*)&h23;
            lp.x = *(uint32_t*)&l01; lp.y = *(uint32_t*)&l23;
            *(uint2*)(ohi + off) = hp;
            *(uint2*)(olo + off) = lp;
        }
    } else {
        float* ob = g_Vp + ((size_t)n * 64 * 512 + f) * 64;
        #pragma unroll
        for (int i = 0; i < 4; i++) {
            float4 v = make_float4(acc[i][0], acc[i][1], acc[i][2], acc[i][3]);
            *(float4*)(ob + (size_t)(ty * 4 + i) * (512 * 64) + tx * 4) = v;
        }
    }
}

// ---------------------------------------------------------------------------
// Kernel 1b: V transpose + bf16 split. [n][e][f][t] -> [n][e][t][f] bf16 x2
// ---------------------------------------------------------------------------
__global__ __launch_bounds__(256) void vtrans_kernel()
{
    __shared__ float sT[64 * PITCH];
    const int fb = blockIdx.x, e = blockIdx.y, n = blockIdx.z;
    const int tid = threadIdx.x;

    const float* src = g_Vp + ((size_t)(n * 64 + e) * 512 + fb * 64) * 64;
    #pragma unroll
    for (int j = 0; j < 4; j++) {
        int idx = tid + j * 256;
        int r = idx >> 4, c = (idx & 15) * 4;
        float4 v = *(const float4*)(src + (size_t)r * 64 + c);
        float* d = &sT[r * PITCH + c];
        d[0] = v.x; d[1] = v.y; d[2] = v.z; d[3] = v.w;
    }
    __syncthreads();

    __nv_bfloat16* dh = g_Vthi + (size_t)(n * 64 + e) * 64 * 512 + fb * 64;
    __nv_bfloat16* dl = g_Vtlo + (size_t)(n * 64 + e) * 64 * 512 + fb * 64;
    #pragma unroll
    for (int j = 0; j < 4; j++) {
        int idx = tid + j * 256;
        int t = idx >> 4, f4 = (idx & 15) * 4;
        float v0 = sT[(f4 + 0) * PITCH + t];
        float v1 = sT[(f4 + 1) * PITCH + t];
        float v2 = sT[(f4 + 2) * PITCH + t];
        float v3 = sT[(f4 + 3) * PITCH + t];
        __nv_bfloat16 h0 = __float2bfloat16(v0), h1 = __float2bfloat16(v1);
        __nv_bfloat16 h2 = __float2bfloat16(v2), h3 = __float2bfloat16(v3);
        __nv_bfloat162 h01, h23, l01, l23;
        h01.x = h0; h01.y = h1; h23.x = h2; h23.y = h3;
        l01.x = __float2bfloat16(v0 - __bfloat162float(h0));
        l01.y = __float2bfloat16(v1 - __bfloat162float(h1));
        l23.x = __float2bfloat16(v2 - __bfloat162float(h2));
        l23.y = __float2bfloat16(v3 - __bfloat162float(h3));
        uint2 hp, lp;
        hp.x = *(uint32_t*)&h01; hp.y = *(uint32_t*)&h23;
        lp.x = *(uint32_t*)&l01; lp.y = *(uint32_t*)&l23;
        *(uint2*)(dh + (size_t)t * 512 + f4) = hp;
        *(uint2*)(dl + (size_t)t * 512 + f4) = lp;
    }
}

#if ATTN_TCGEN
// Load one K/V chunk (bf16 hi/lo) into smem buffer b. 256 threads.
__device__ __forceinline__ void load_kv_chunk(
    char* smem, const __nv_bfloat16* Khg, const __nv_bfloat16* Klg,
    const __nv_bfloat16* Vhg, const __nv_bfloat16* Vlg,
    int c, int b, int tid)
{
    const __nv_bfloat16* kh = Khg + c * 64 * 64;
    const __nv_bfloat16* kl = Klg + c * 64 * 64;
    char* kbase = smem + SM_K + b * 16384;
    char* vbase = smem + SM_V + b * 16384;
    #pragma unroll
    for (int j = 0; j < 2; j++) {
        int idx = tid + j * 256;            // 0..511 16B units
        int r = idx >> 3, c16 = idx & 7;
        uint32_t sw = swz((uint32_t)(r * 128 + c16 * 16));
        uint4 a  = *(const uint4*)(kh + r * 64 + c16 * 8);
        uint4 bb = *(const uint4*)(kl + r * 64 + c16 * 8);
        *(uint4*)(kbase + sw) = a;
        *(uint4*)(kbase + 8192 + sw) = bb;
        uint4 vh = *(const uint4*)(Vhg + (size_t)r * 512 + c * 64 + c16 * 8);
        uint4 vl = *(const uint4*)(Vlg + (size_t)r * 512 + c * 64 + c16 * 8);
        *(uint4*)(vbase + sw) = vh;
        *(uint4*)(vbase + 8192 + sw) = vl;
    }
}

// 3-pass split GEMM: (Ahi,Bhi) + (Ahi,Blo) + (Alo,Bhi). 12 dispatches.
__device__ __forceinline__ void issue_3pass(uint32_t dst, uint64_t ahi, uint64_t alo,
                                            uint64_t bhi, uint64_t blo, bool accum)
{
    #pragma unroll
    for (int p = 0; p < 3; p++) {
        uint64_t A = (p == 2) ? alo : ahi;
        uint64_t B = (p == 1) ? blo : bhi;
        #pragma unroll
        for (int s = 0; s < 4; s++)
            mma_bf16_ss(dst, A + s * 2, B + s * 2, IDESC_BF16,
                        accum || !(p == 0 && s == 0));
    }
}
#endif

// ---------------------------------------------------------------------------
// Kernel 2: attention. grid (4 qtile, 64 e, 8 n), block 256.
// S ping-pong in TMEM with one mbarrier PER BUFFER (waiter never lags >=2
// phases on a single barrier -> no parity aliasing). GEMM1(kc+1) issued
// before softmax(kc) so it overlaps the scalar phase. 8 warps split the 64
// S-columns (warps 0-3: cols 0-31, warps 4-7: cols 32-63).
// ---------------------------------------------------------------------------
__global__ void __launch_bounds__(256, 1) attn_tc_kernel()
{
    extern __shared__ char smem[];
    const int tid = threadIdx.x;
    const int qb = blockIdx.x, e = blockIdx.y, n = blockIdx.z;
    const size_t plane = (size_t)(n * 64 + e);
    const size_t qk_base = plane * 512 * 64;   // [f][t]
    const __nv_bfloat16* Qhg = g_Qhi + qk_base + (size_t)qb * 128 * 64;
    const __nv_bfloat16* Qlg = g_Qlo + qk_base + (size_t)qb * 128 * 64;
    const __nv_bfloat16* Khg = g_Khi + qk_base;
    const __nv_bfloat16* Klg = g_Klo + qk_base;
    const __nv_bfloat16* Vhg = g_Vthi + plane * 64 * 512;  // [t][f]
    const __nv_bfloat16* Vlg = g_Vtlo + plane * 64 * 512;

#if ATTN_TCGEN
    const uint32_t sb = smem_u32(smem);
    const int wid = tid >> 5, lid = tid & 31;
    const int row = (wid & 3) * 32 + lid;     // q row this thread owns
    const int cb  = (wid >> 2) * 32;          // column half: 0 or 32

    if (wid == 0) TC_ALLOC(sb + SM_TMEM, 256);
    if (tid == 0) {
        MBAR_INIT(sb + SM_MBS0, 1);
        MBAR_INIT(sb + SM_MBS1, 1);
        MBAR_INIT(sb + SM_MB2, 1);
    }
    __syncthreads();
    uint32_t tmem;
    asm volatile("ld.shared.b32 %0, [%1];" : "=r"(tmem) : "r"(sb + SM_TMEM));
    uint32_t tS[2]; tS[0] = tmem; tS[1] = tmem + 64;
    uint32_t mbS[2]; mbS[0] = sb + SM_MBS0; mbS[1] = sb + SM_MBS1;
    const uint32_t tO = tmem + 128;

    // Prologue: Q tiles + chunk 0 of K/V
    #pragma unroll
    for (int j = 0; j < 4; j++) {
        int idx = tid + j * 256;          // 0..1023 16B units
        int r = idx >> 3, c16 = idx & 7;
        uint32_t sw = swz((uint32_t)(r * 128 + c16 * 16));
        uint4 qh = *(const uint4*)(Qhg + r * 64 + c16 * 8);
        uint4 ql = *(const uint4*)(Qlg + r * 64 + c16 * 8);
        *(uint4*)(smem + SM_QHI + sw) = qh;
        *(uint4*)(smem + SM_QLO + sw) = ql;
    }
    load_kv_chunk(smem, Khg, Klg, Vhg, Vlg, 0, 0, tid);
    FENCE_ASYNC();
    TC_FENCE_BEFORE();
    __syncthreads();

    const uint64_t dQh = make_desc(sb + SM_QHI), dQl = make_desc(sb + SM_QLO);
    const uint64_t dPh = make_desc(sb + SM_PHI), dPl = make_desc(sb + SM_PLO);
    uint64_t dKh[2], dKl[2], dVh[2], dVl[2];
    #pragma unroll
    for (int b = 0; b < 2; b++) {
        dKh[b] = make_desc(sb + SM_K + b * 16384);
        dKl[b] = make_desc(sb + SM_K + b * 16384 + 8192);
        dVh[b] = make_desc(sb + SM_V + b * 16384);
        dVl[b] = make_desc(sb + SM_V + b * 16384 + 8192);
    }

    // GEMM1(0) -> S0, commit to mbS[0]
    if (wid == 0) {
        TC_FENCE_AFTER();
        if (elect_one()) {
            issue_3pass(tS[0], dQh, dQl, dKh[0], dKl[0], false);
            TC_COMMIT(mbS[0]);
        }
    }

    float l_part = 0.0f;
    uint32_t sreg[32];

    for (int kc = 0; kc < 8; kc++) {
        // V buf (kc+1)&1 and P tile freed by GEMM2(kc-1)
        if (kc > 0) MBAR_WAIT(sb + SM_MB2, (kc - 1) & 1);
        if (kc < 7) {
            load_kv_chunk(smem, Khg, Klg, Vhg, Vlg, kc + 1, (kc + 1) & 1, tid);
            FENCE_ASYNC();
        }
        __syncthreads();
        // Issue GEMM1(kc+1) NOW -> overlaps softmax(kc). Commits to its own
        // barrier mbS[(kc+1)&1]; waiter below lags <=1 phase per barrier.
        if (kc < 7 && wid == 0) {
            TC_FENCE_AFTER();
            if (elect_one()) {
                issue_3pass(tS[(kc + 1) & 1], dQh, dQl,
                            dKh[(kc + 1) & 1], dKl[(kc + 1) & 1], false);
                TC_COMMIT(mbS[(kc + 1) & 1]);
            }
        }

        // S(kc) ready: barrier mbS[kc&1], phase (kc>>1), parity (kc>>1)&1
        MBAR_WAIT(mbS[kc & 1], (kc >> 1) & 1);
        TC_FENCE_AFTER();
        TC_LD_X32(sreg, tS[kc & 1] + cb);
        TC_WAIT_LD();

        float l_loc = 0.0f;
        #pragma unroll
        for (int c = 0; c < 32; c++) {
            float sv = __uint_as_float(sreg[c]);
            float pe = __expf(sv * 0.125f);
            sreg[c] = __float_as_uint(pe);
            l_loc += pe;
        }
        l_part += l_loc;

        // pack P (row, cols cb..cb+31) to bf16 hi/lo, swizzled 16B stores
        #pragma unroll
        for (int g = 0; g < 4; g++) {
            uint32_t hw[4], lw[4];
            #pragma unroll
            for (int x = 0; x < 4; x++) {
                float p0 = __uint_as_float(sreg[g * 8 + x * 2]);
                float p1 = __uint_as_float(sreg[g * 8 + x * 2 + 1]);
                uint32_t hi;
                asm("cvt.rn.bf16x2.f32 %0, %1, %2;" : "=r"(hi) : "f"(p1), "f"(p0));
                float hf0 = __uint_as_float(hi << 16);
                float hf1 = __uint_as_float(hi & 0xFFFF0000u);
                uint32_t lo;
                asm("cvt.rn.bf16x2.f32 %0, %1, %2;"
                    : "=r"(lo) : "f"(p1 - hf1), "f"(p0 - hf0));
                hw[x] = hi; lw[x] = lo;
            }
            uint32_t sw = swz((uint32_t)(row * 128 + cb * 2 + g * 16));
            *(uint4*)(smem + SM_PHI + sw) = make_uint4(hw[0], hw[1], hw[2], hw[3]);
            *(uint4*)(smem + SM_PLO + sw) = make_uint4(lw[0], lw[1], lw[2], lw[3]);
        }
        TC_FENCE_BEFORE();
        FENCE_ASYNC();
        __syncthreads();

        // GEMM2(kc): O += P * V (accumulate across chunks)
        if (wid == 0) {
            TC_FENCE_AFTER();
            if (elect_one()) {
                issue_3pass(tO, dPh, dPl, dVh[kc & 1], dVl[kc & 1], kc > 0);
                TC_COMMIT(sb + SM_MB2);
            }
        }
    }

    MBAR_WAIT(sb + SM_MB2, 1);   // 8th GEMM2 commit => phase 7, parity 1
    TC_FENCE_AFTER();

    // combine row sums (pair: tid and tid^128 share a q-row)
    *(float*)(smem + SM_RED + tid * 4) = l_part;
    TC_LD_X32(sreg, tO + cb);
    TC_WAIT_LD();
    TC_FENCE_BEFORE();
    __syncthreads();
    const float l_sum = l_part + *(float*)(smem + SM_RED + (tid ^ 128) * 4);

    const float inv = 1.0f / l_sum;
    float* Og = g_Op + plane * 512 * 64 + (size_t)qb * 128 * 64
              + (size_t)row * 64 + cb;
    #pragma unroll
    for (int c4 = 0; c4 < 32; c4 += 4) {
        float4 ov = make_float4(__uint_as_float(sreg[c4 + 0]) * inv,
                                __uint_as_float(sreg[c4 + 1]) * inv,
                                __uint_as_float(sreg[c4 + 2]) * inv,
                                __uint_as_float(sreg[c4 + 3]) * inv);
        *(float4*)(Og + c4) = ov;
    }

    __syncthreads();
    if (wid == 0) { TC_RELINQ(); TC_DEALLOC(tmem, 256); }

#else   // ------------------- scalar fallback (non-'a' target) ---------------
    float* sK = (float*)smem;          // [64][65]
    float* sV = sK + 64 * 65;          // [64][65]

    float qreg[64];
    if (tid < 128) {
        #pragma unroll
        for (int t = 0; t < 64; t++)
            qreg[t] = __bfloat162float(Qhg[tid * 64 + t]) +
                      __bfloat162float(Qlg[tid * 64 + t]);
    }

    float o[64];
    #pragma unroll
    for (int t = 0; t < 64; t++) o[t] = 0.0f;
    float l_sum = 0.0f;
    const float* Vg = g_Vp + plane * 512 * 64;

    for (int kc = 0; kc < 8; kc++) {
        __syncthreads();
        #pragma unroll
        for (int i = tid; i < 1024; i += 256) {
            int r = i >> 4, c = (i & 15) * 4;
            size_t off = (size_t)(kc * 64 + r) * 64 + c;
            #pragma unroll
            for (int j = 0; j < 4; j++)
                sK[r * 65 + c + j] = __bfloat162float(Khg[off + j]) +
                                     __bfloat162float(Klg[off + j]);
            float4 vv = *(const float4*)(Vg + off);
            float* dv = &sV[r * 65 + c];
            dv[0] = vv.x; dv[1] = vv.y; dv[2] = vv.z; dv[3] = vv.w;
        }
        __syncthreads();

        if (tid < 128) {
            for (int k = 0; k < 64; k++) {
                float s = 0.0f;
                #pragma unroll 16
                for (int t = 0; t < 64; t++) s = fmaf(qreg[t], sK[k * 65 + t], s);
                float p = __expf(s * 0.125f);
                l_sum += p;
                #pragma unroll 16
                for (int t = 0; t < 64; t++) o[t] = fmaf(p, sV[k * 65 + t], o[t]);
            }
        }
    }

    if (tid < 128) {
        const float inv = 1.0f / l_sum;
        float* Og = g_Op + plane * 512 * 64 + (size_t)qb * 128 * 64
                  + (size_t)tid * 64;
        #pragma unroll
        for (int c = 0; c < 64; c++) Og[c] = o[c] * inv;
    }
#endif
}

// ---------------------------------------------------------------------------
// Kernel 3: output projection + transpose back.
// ---------------------------------------------------------------------------
__global__ __launch_bounds__(256) void out_kernel(
    const float* __restrict__ Wo, const float* __restrict__ bo,
    float* __restrict__ out)
{
    __shared__ float sO[64 * PITCH];
    __shared__ float sW[64 * PITCH];
    __shared__ float sb_[64];

    const int q = blockIdx.x, n = blockIdx.y;
    const int tid = threadIdx.x, ty = tid >> 4, tx = tid & 15;

    #pragma unroll
    for (int i = tid; i < 4096; i += 256)
        sW[(i >> 6) * PITCH + (i & 63)] = Wo[i];
    if (tid < 64) sb_[tid] = bo[tid];

    #pragma unroll
    for (int i = tid; i < 1024; i += 256) {
        int er = i >> 4, c = (i & 15) * 4;
        float4 v = *(const float4*)(g_Op + ((size_t)(n * 64 + er) * 512 + q) * 64 + c);
        float* d = &sO[er * PITCH + c];
        d[0] = v.x; d[1] = v.y; d[2] = v.z; d[3] = v.w;
    }
    __syncthreads();

    float acc[4][4] = {};
    #pragma unroll
    for (int e = 0; e < 64; e++) {
        float a[4], b[4];
        #pragma unroll
        for (int i = 0; i < 4; i++) a[i] = sO[e * PITCH + ty * 4 + i];
        #pragma unroll
        for (int j = 0; j < 4; j++) b[j] = sW[(tx * 4 + j) * PITCH + e];
        #pragma unroll
        for (int i = 0; i < 4; i++)
            #pragma unroll
            for (int j = 0; j < 4; j++)
                acc[i][j] = fmaf(a[i], b[j], acc[i][j]);
    }

    #pragma unroll
    for (int i = 0; i < 4; i++) {
        int t = ty * 4 + i;
        float4 v = make_float4(acc[i][0] + sb_[tx * 4 + 0],
                               acc[i][1] + sb_[tx * 4 + 1],
                               acc[i][2] + sb_[tx * 4 + 2],
                               acc[i][3] + sb_[tx * 4 + 3]);
        *(float4*)(out + ((size_t)(n * 64 + t) * 512 + q) * 64 + tx * 4) = v;
    }
}

// ---------------------------------------------------------------------------
extern "C" void kernel_launch(void* const* d_in, const int* in_sizes, int n_in,
                              void* d_out, int out_size)
{
    const float* value = (const float*)d_in[0];
    const float* key   = (const float*)d_in[1];
    const float* query = (const float*)d_in[2];
    const float* Wv    = (const float*)d_in[3];
    const float* Wk    = (const float*)d_in[4];
    const float* Wq    = (const float*)d_in[5];
    const float* Wo    = (const float*)d_in[6];
    const float* bo    = (const float*)d_in[7];
    float* out = (float*)d_out;

    cudaFuncSetAttribute(attn_tc_kernel,
                         cudaFuncAttributeMaxDynamicSharedMemorySize, SM_TOTAL);

    dim3 g1(512, 8, 3);
    proj_kernel<<<g1, 256>>>(query, key, value, Wq, Wk, Wv);

    dim3 g1b(8, 64, 8);
    vtrans_kernel<<<g1b, 256>>>();

    dim3 g2(4, 64, 8);
    attn_tc_kernel<<<g2, 256, SM_TOTAL>>>();

    dim3 g3(512, 8);
    out_kernel<<<g3, 256>>>(Wo, bo, out);
}